// round 1
// baseline (speedup 1.0000x reference)
#include <cuda_runtime.h>
#include <cuda_fp16.h>
#include <cstdint>

#define NROWS 16384
#define DDIM  256
#define BM 128
#define BN 128
#define BK 32
#define SM_STRIDE 40   // BK + 8 halfs pad -> 80B row stride, conflict-free ldmatrix

// Static device scratch (no allocations allowed)
__device__ __half g_imgH[NROWS * DDIM];
__device__ __half g_txtH[NROWS * DDIM];
__device__ double g_partials[(NROWS / BM) * (NROWS / BN)];

static __device__ __forceinline__ uint32_t smem_u32(const void* p) {
    return (uint32_t)__cvta_generic_to_shared(p);
}

static __device__ __forceinline__ void ldsm_x4(uint32_t& r0, uint32_t& r1,
                                               uint32_t& r2, uint32_t& r3,
                                               uint32_t addr) {
    asm volatile("ldmatrix.sync.aligned.m8n8.x4.shared.b16 {%0,%1,%2,%3}, [%4];\n"
                 : "=r"(r0), "=r"(r1), "=r"(r2), "=r"(r3) : "r"(addr));
}

static __device__ __forceinline__ void mma16816(float& c0, float& c1, float& c2, float& c3,
                                                uint32_t a0, uint32_t a1, uint32_t a2, uint32_t a3,
                                                uint32_t b0, uint32_t b1) {
    asm volatile(
        "mma.sync.aligned.m16n8k16.row.col.f32.f16.f16.f32 "
        "{%0,%1,%2,%3}, {%4,%5,%6,%7}, {%8,%9}, {%0,%1,%2,%3};\n"
        : "+f"(c0), "+f"(c1), "+f"(c2), "+f"(c3)
        : "r"(a0), "r"(a1), "r"(a2), "r"(a3), "r"(b0), "r"(b1));
}

static __device__ __forceinline__ float softplus_f(float x) {
    // log(1 + e^x), stable; fast-math intrinsics (MUFU EX2/LG2)
    return fmaxf(x, 0.0f) + __logf(1.0f + __expf(-fabsf(x)));
}

// ---------------------------------------------------------------------------
// Kernel 1: L2-normalize rows, write fp16. One warp per row.
// grid: (NROWS/8, 2)  block: 256
// ---------------------------------------------------------------------------
__global__ void normalize_kernel(const float* __restrict__ img,
                                 const float* __restrict__ txt) {
    int warp = threadIdx.x >> 5;
    int lane = threadIdx.x & 31;
    int row  = blockIdx.x * 8 + warp;
    const float* src = (blockIdx.y == 0) ? img : txt;
    __half* dst      = (blockIdx.y == 0) ? g_imgH : g_txtH;

    const float4* p = reinterpret_cast<const float4*>(src + (size_t)row * DDIM + lane * 8);
    float4 v0 = p[0];
    float4 v1 = p[1];
    float ss = v0.x * v0.x + v0.y * v0.y + v0.z * v0.z + v0.w * v0.w
             + v1.x * v1.x + v1.y * v1.y + v1.z * v1.z + v1.w * v1.w;
#pragma unroll
    for (int o = 16; o > 0; o >>= 1) ss += __shfl_xor_sync(0xffffffffu, ss, o);
    float inv = 1.0f / fmaxf(sqrtf(ss), 1e-12f);

    __half2 h0 = __floats2half2_rn(v0.x * inv, v0.y * inv);
    __half2 h1 = __floats2half2_rn(v0.z * inv, v0.w * inv);
    __half2 h2 = __floats2half2_rn(v1.x * inv, v1.y * inv);
    __half2 h3 = __floats2half2_rn(v1.z * inv, v1.w * inv);
    uint4 w;
    w.x = *reinterpret_cast<unsigned*>(&h0);
    w.y = *reinterpret_cast<unsigned*>(&h1);
    w.z = *reinterpret_cast<unsigned*>(&h2);
    w.w = *reinterpret_cast<unsigned*>(&h3);
    *reinterpret_cast<uint4*>(dst + (size_t)row * DDIM + lane * 8) = w;
}

// ---------------------------------------------------------------------------
// Kernel 2: fused GEMM + softplus reduction.
// Block tile 128x128, 8 warps in 4x2 (warp tile 32x64), BK=32 double-buffered.
// grid: (128, 128)  block: 256
// ---------------------------------------------------------------------------
__global__ __launch_bounds__(256, 2) void siglip_gemm(const float* __restrict__ tprime,
                                                      const float* __restrict__ biasp) {
    __shared__ __half As[2][BM][SM_STRIDE];
    __shared__ __half Bs[2][BM][SM_STRIDE];
    __shared__ float red[8];

    const int tid  = threadIdx.x;
    const int lane = tid & 31;
    const int w    = tid >> 5;
    const int wr   = w >> 1;   // 0..3 : 32-row slab
    const int wc   = w & 1;    // 0..1 : 64-col slab
    const int bx   = blockIdx.x;
    const int by   = blockIdx.y;

    const __half* Ag = g_imgH + (size_t)(by * BM) * DDIM;
    const __half* Bg = g_txtH + (size_t)(bx * BM) * DDIM;

    const int lrow  = tid >> 1;       // 0..127
    const int lhalf = tid & 1;        // which 16-half chunk of the BK=32 row

    // ldmatrix source coordinates (fixed per thread)
    const int aRow  = wr * 32 + (lane & 15);
    const int aKsel = (lane >> 4) * 8;
    const int bRow  = wc * 64 + (lane & 7) + ((lane & 16) ? 8 : 0);
    const int bKsel = (lane & 8) ? 8 : 0;

    float acc[2][8][4];
#pragma unroll
    for (int i = 0; i < 2; i++)
#pragma unroll
        for (int j = 0; j < 8; j++)
#pragma unroll
            for (int k = 0; k < 4; k++) acc[i][j][k] = 0.0f;

    // --- prologue: load k-chunk 0 into stage 0 ---
    {
        const uint4* pa = reinterpret_cast<const uint4*>(Ag + (size_t)lrow * DDIM + lhalf * 16);
        const uint4* pb = reinterpret_cast<const uint4*>(Bg + (size_t)lrow * DDIM + lhalf * 16);
        uint4 a0 = pa[0], a1 = pa[1], b0 = pb[0], b1 = pb[1];
        *reinterpret_cast<uint4*>(&As[0][lrow][lhalf * 16])     = a0;
        *reinterpret_cast<uint4*>(&As[0][lrow][lhalf * 16 + 8]) = a1;
        *reinterpret_cast<uint4*>(&Bs[0][lrow][lhalf * 16])     = b0;
        *reinterpret_cast<uint4*>(&Bs[0][lrow][lhalf * 16 + 8]) = b1;
    }
    __syncthreads();

    const int NCHUNK = DDIM / BK;  // 8
#pragma unroll
    for (int c = 0; c < NCHUNK; c++) {
        uint4 na0, na1, nb0, nb1;
        if (c < NCHUNK - 1) {
            int k0 = (c + 1) * BK;
            const uint4* pa = reinterpret_cast<const uint4*>(Ag + (size_t)lrow * DDIM + k0 + lhalf * 16);
            const uint4* pb = reinterpret_cast<const uint4*>(Bg + (size_t)lrow * DDIM + k0 + lhalf * 16);
            na0 = pa[0]; na1 = pa[1]; nb0 = pb[0]; nb1 = pb[1];
        }

        const int s = c & 1;
#pragma unroll
        for (int ks = 0; ks < 2; ks++) {
            // A fragments: 2 m-tiles of 16x16
            uint32_t a[2][4];
#pragma unroll
            for (int mi = 0; mi < 2; mi++) {
                uint32_t addr = smem_u32(&As[s][aRow + mi * 16][ks * 16 + aKsel]);
                ldsm_x4(a[mi][0], a[mi][1], a[mi][2], a[mi][3], addr);
            }
            // B fragments: 4 ldmatrix.x4, each feeds 2 n8-tiles
#pragma unroll
            for (int np = 0; np < 4; np++) {
                uint32_t b0, b1, b2, b3;
                uint32_t addr = smem_u32(&Bs[s][bRow + np * 16][ks * 16 + bKsel]);
                ldsm_x4(b0, b1, b2, b3, addr);
#pragma unroll
                for (int mi = 0; mi < 2; mi++) {
                    mma16816(acc[mi][np * 2][0], acc[mi][np * 2][1],
                             acc[mi][np * 2][2], acc[mi][np * 2][3],
                             a[mi][0], a[mi][1], a[mi][2], a[mi][3], b0, b1);
                    mma16816(acc[mi][np * 2 + 1][0], acc[mi][np * 2 + 1][1],
                             acc[mi][np * 2 + 1][2], acc[mi][np * 2 + 1][3],
                             a[mi][0], a[mi][1], a[mi][2], a[mi][3], b2, b3);
                }
            }
        }

        if (c < NCHUNK - 1) {
            const int ns = (c + 1) & 1;
            *reinterpret_cast<uint4*>(&As[ns][lrow][lhalf * 16])     = na0;
            *reinterpret_cast<uint4*>(&As[ns][lrow][lhalf * 16 + 8]) = na1;
            *reinterpret_cast<uint4*>(&Bs[ns][lrow][lhalf * 16])     = nb0;
            *reinterpret_cast<uint4*>(&Bs[ns][lrow][lhalf * 16 + 8]) = nb1;
        }
        __syncthreads();
    }

    // --- fused epilogue: z = scale*dot + b; sum softplus(-label*z) ---
    const float scale = __expf(*tprime);
    const float bias  = *biasp;

    const int rbase = by * BM + wr * 32 + (lane >> 2);
    const int cbase = bx * BN + wc * 64 + 2 * (lane & 3);

    float lsum = 0.0f;
#pragma unroll
    for (int mi = 0; mi < 2; mi++) {
#pragma unroll
        for (int nt = 0; nt < 8; nt++) {
            int r0 = rbase + mi * 16;
            int c0 = cbase + nt * 8;
            float z;
            z = fmaf(scale, acc[mi][nt][0], bias);
            lsum += softplus_f((r0 == c0) ? -z : z);
            z = fmaf(scale, acc[mi][nt][1], bias);
            lsum += softplus_f((r0 == c0 + 1) ? -z : z);
            z = fmaf(scale, acc[mi][nt][2], bias);
            lsum += softplus_f((r0 + 8 == c0) ? -z : z);
            z = fmaf(scale, acc[mi][nt][3], bias);
            lsum += softplus_f((r0 + 8 == c0 + 1) ? -z : z);
        }
    }

#pragma unroll
    for (int o = 16; o > 0; o >>= 1) lsum += __shfl_xor_sync(0xffffffffu, lsum, o);
    if (lane == 0) red[w] = lsum;
    __syncthreads();
    if (tid == 0) {
        float s = 0.0f;
#pragma unroll
        for (int i = 0; i < 8; i++) s += red[i];
        g_partials[by * gridDim.x + bx] = (double)s;
    }
}

// ---------------------------------------------------------------------------
// Kernel 3: deterministic final reduction of 16384 block partials.
// ---------------------------------------------------------------------------
__global__ void reduce_kernel(float* __restrict__ out) {
    __shared__ double sh[256];
    double s = 0.0;
    for (int i = threadIdx.x; i < (NROWS / BM) * (NROWS / BN); i += 256)
        s += g_partials[i];
    sh[threadIdx.x] = s;
    __syncthreads();
    for (int o = 128; o > 0; o >>= 1) {
        if (threadIdx.x < o) sh[threadIdx.x] += sh[threadIdx.x + o];
        __syncthreads();
    }
    if (threadIdx.x == 0) out[0] = (float)(sh[0] / (double)NROWS);
}

extern "C" void kernel_launch(void* const* d_in, const int* in_sizes, int n_in,
                              void* d_out, int out_size) {
    const float* img    = (const float*)d_in[0];
    const float* txt    = (const float*)d_in[1];
    const float* tprime = (const float*)d_in[2];
    const float* bias   = (const float*)d_in[3];
    float* out = (float*)d_out;

    normalize_kernel<<<dim3(NROWS / 8, 2), 256>>>(img, txt);
    siglip_gemm<<<dim3(NROWS / BN, NROWS / BM), 256>>>(tprime, bias);
    reduce_kernel<<<1, 256>>>(out);
}